// round 8
// baseline (speedup 1.0000x reference)
#include <cuda_runtime.h>
#include <cstdint>
#include <cstddef>

// Dims fixed: B=32, S=512, H=1024, fp32.
#define Bb   32
#define Ss   512
#define Hh   1024
#define NCTA 128
#define NTHR 256

// ---- device scratch (allocation-free rule: __device__ globals) -------------
// Blocked-transposed weights: WT[m][kq][c][j] = W_m[c][4*kq+j], m in {hb,r,b}.
// float4 index = (m*256 + kq)*1024 + c. 12 MB total (L2-resident).
__device__ __align__(16) float4 g_WT4[3 * 256 * 1024];
__device__ __align__(16) float g_Bi[(size_t)Ss * Bb * Hh]; // tanh(x_t W_b^T + b_b), [t][b][h]
__device__ __align__(16) float g_h [Bb * Hh];
__device__ __align__(16) float g_hi[Bb * Hh];
__device__ __align__(16) float g_ri[Bb * Hh];
__device__ unsigned g_bar;

__global__ void init_kernel() {
    int i = blockIdx.x * blockDim.x + threadIdx.x;
    if (i < Bb * Hh) g_h[i] = 0.0f;
    if (i == 0) g_bar = 0u;
}

// ---------------------------------------------------------------------------
// XLA EmitFastTanh, FMA variant (with_fma = true): clamp +-7.99881172180175781,
// FMA Horner, |x| < 0.0004 passthrough, IEEE divide. This is the form XLA
// emits on any FMA-capable target (aarch64 NEON CPU, and the GPU elemental
// emitter). All ops pinned with _rn intrinsics.
__device__ __forceinline__ float xla_tanh(float x) {
    float z = fminf(x, 7.99881172180175781f);
    z = fmaxf(z, -7.99881172180175781f);
    float x2 = __fmul_rn(z, z);
    float p = __fmaf_rn(x2, -2.76076847742355e-16f, 2.00018790482477e-13f);
    p = __fmaf_rn(x2, p, -8.60467152213735e-11f);
    p = __fmaf_rn(x2, p,  5.12229709037114e-08f);
    p = __fmaf_rn(x2, p,  1.48572235717979e-05f);
    p = __fmaf_rn(x2, p,  6.37261928875436e-04f);
    p = __fmaf_rn(x2, p,  4.89352455891786e-03f);
    p = __fmul_rn(z, p);
    float q = __fmaf_rn(x2, 1.19825839466702e-06f, 1.18534705686654e-04f);
    q = __fmaf_rn(x2, q, 2.26843463243900e-03f);
    q = __fmaf_rn(x2, q, 4.89352518554385e-03f);
    return (fabsf(x) < 0.0004f) ? x : __fdiv_rn(p, q);
}

// ---------------------------------------------------------------------------
// Weight transpose into k-quad-blocked layout. Pure copy (bit-free).
__global__ void transpose_kernel(const float* __restrict__ Whb,
                                 const float* __restrict__ Wr,
                                 const float* __restrict__ Wb) {
    int i = blockIdx.x * blockDim.x + threadIdx.x;   // 0 .. 3*262144-1
    if (i >= 3 * 262144) return;
    int m  = i >> 18;
    int r  = i & 262143;
    int kq = r >> 10;
    int c  = r & 1023;
    const float* src = (m == 0) ? Whb : (m == 1) ? Wr : Wb;
    g_WT4[i] = ((const float4*)src)[c * 256 + kq];
}

// ---------------------------------------------------------------------------
// Bi precompute. Block = (t, c-block of 256). Thread owns column c and all 32
// batch rows: 32 register accumulators, each a PURE ascending-k fma chain
// (bit-identical order to the in-step dot). x panel staged in SMEM.
__global__ __launch_bounds__(NTHR, 1) void bi_kernel(
    const float* __restrict__ x, const float* __restrict__ bbias)
{
    __shared__ float xs[Bb][128];
    const int tid = threadIdx.x;
    const int t   = blockIdx.y;
    const int c   = blockIdx.x * NTHR + tid;
    const float4* wt = g_WT4 + 2 * 262144 + c;   // W_b slice, stride 1024 per kq

    float acc[Bb];
    #pragma unroll
    for (int b = 0; b < Bb; b++) acc[b] = 0.0f;

    for (int kp = 0; kp < 8; kp++) {             // 8 panels of 128 k
        __syncthreads();
        #pragma unroll
        for (int j = 0; j < 4; j++) {            // stage x[b][t][k0..k0+127]
            int i  = tid + j * NTHR;             // 0..1023 float4s
            int b  = i >> 5;
            int kl = i & 31;
            ((float4*)&xs[b][0])[kl] =
                *(const float4*)(x + ((size_t)b * Ss + t) * Hh + kp * 128 + kl * 4);
        }
        __syncthreads();
        #pragma unroll 1
        for (int kl = 0; kl < 32; kl++) {
            float4 w = wt[(kp * 32 + kl) * 1024];
            #pragma unroll
            for (int b = 0; b < Bb; b++) {
                float4 a = *(const float4*)&xs[b][kl * 4];
                acc[b] = __fmaf_rn(a.x, w.x, acc[b]);
                acc[b] = __fmaf_rn(a.y, w.y, acc[b]);
                acc[b] = __fmaf_rn(a.z, w.z, acc[b]);
                acc[b] = __fmaf_rn(a.w, w.w, acc[b]);
            }
        }
    }

    float bias = bbias[c];
    #pragma unroll
    for (int b = 0; b < Bb; b++)
        g_Bi[((size_t)t * Bb + b) * Hh + c] = xla_tanh(__fadd_rn(acc[b], bias));
}

// ---------------------------------------------------------------------------
// Grid barrier: release-fence + atomic arrive, acquire poll by tid0.
__device__ __forceinline__ void gsync(unsigned* epoch) {
    *epoch += NCTA;
    __syncthreads();
    if (threadIdx.x == 0) {
        __threadfence();
        atomicAdd(&g_bar, 1u);
        unsigned e = *epoch, v;
        do {
            asm volatile("ld.acquire.gpu.u32 %0, [%1];" : "=r"(v) : "l"(&g_bar));
        } while (v < e);
    }
    __syncthreads();
}

// Canonical dot: single accumulator, ascending-k fp32 fma chain against the
// blocked-transposed weight slice. Lane = c => coalesced weight loads;
// activation loads warp-uniform (L1 broadcast).
__device__ __forceinline__ float dot_wt(const float4* __restrict__ wt,
                                        const float* __restrict__ v) {
    float acc = 0.0f;
    const float4* v4 = (const float4*)v;
    #pragma unroll 8
    for (int kq = 0; kq < 256; kq++) {
        float4 w = wt[kq * 1024];
        float4 a = v4[kq];
        acc = __fmaf_rn(a.x, w.x, acc);
        acc = __fmaf_rn(a.y, w.y, acc);
        acc = __fmaf_rn(a.z, w.z, acc);
        acc = __fmaf_rn(a.w, w.w, acc);
    }
    return acc;
}

// Same chain with the literal (ri + p_t) elementwise add folded in: fl(r+p)
// is a single rounded add (order-free), the chain order over k is untouched.
__device__ __forceinline__ float dot_wt_add(const float4* __restrict__ wt,
                                            const float* __restrict__ r,
                                            const float* __restrict__ p) {
    float acc = 0.0f;
    const float4* r4 = (const float4*)r;
    const float4* p4 = (const float4*)p;
    #pragma unroll 8
    for (int kq = 0; kq < 256; kq++) {
        float4 w = wt[kq * 1024];
        float4 a = r4[kq];
        float4 q = p4[kq];
        acc = __fmaf_rn(__fadd_rn(a.x, q.x), w.x, acc);
        acc = __fmaf_rn(__fadd_rn(a.y, q.y), w.y, acc);
        acc = __fmaf_rn(__fadd_rn(a.z, q.z), w.z, acc);
        acc = __fmaf_rn(__fadd_rn(a.w, q.w), w.w, acc);
    }
    return acc;
}

// ---------------------------------------------------------------------------
// Sequential recurrence. 128 CTAs x 256 threads = one thread per output (b,c).
// CTA = 32 consecutive c (lanes) x 8 b (warps). 3 grid barriers per step.
__global__ __launch_bounds__(NTHR, 1) void seq_kernel(
    const float* __restrict__ pe,
    const float* __restrict__ bb, const float* __restrict__ bhb,
    const float* __restrict__ br,
    float* __restrict__ out)
{
    const int lane = threadIdx.x & 31;
    const int w    = threadIdx.x >> 5;
    const int c    = (blockIdx.x & 31) * 32 + lane;
    const int b    = (blockIdx.x >> 5) * 8 + w;
    const int o    = b * Hh + c;

    const float4* wt_hb = g_WT4 + 0 * 262144 + c;
    const float4* wt_r  = g_WT4 + 1 * 262144 + c;
    const float4* wt_b  = g_WT4 + 2 * 262144 + c;
    const float bias_hb = bhb[c];
    const float bias_r  = br[c];
    const float bias_b  = bb[c];

    unsigned epoch = 0u;
    float hi = 0.0f;

    #pragma unroll 1
    for (int t = 0; t < Ss; t++) {
        // sub 1: hi = tanh(h @ W_hb^T + b_hb) + bi[t]
        float z = dot_wt(wt_hb, g_h + (size_t)b * Hh);
        hi = __fadd_rn(xla_tanh(__fadd_rn(z, bias_hb)),
                       g_Bi[((size_t)t * Bb + b) * Hh + c]);
        g_hi[o] = hi;
        gsync(&epoch);

        // sub 2: ri = tanh(hi @ W_r^T + b_r)
        z = dot_wt(wt_r, g_hi + (size_t)b * Hh);
        g_ri[o] = xla_tanh(__fadd_rn(z, bias_r));
        gsync(&epoch);

        // sub 3: h = hi + tanh((ri + p_t) @ W_b^T + b_b)
        z = dot_wt_add(wt_b, g_ri + (size_t)b * Hh,
                       pe + ((size_t)b * Ss + t) * Hh);
        float hn = __fadd_rn(hi, xla_tanh(__fadd_rn(z, bias_b)));
        g_h[o] = hn;
        if (t == Ss - 1) out[o] = hn;
        gsync(&epoch);
    }
}

// ---------------------------------------------------------------------------
extern "C" void kernel_launch(void* const* d_in, const int* in_sizes, int n_in,
                              void* d_out, int out_size) {
    const float* x   = (const float*)d_in[0];
    const float* pe  = (const float*)d_in[1];
    const float* Wb  = (const float*)d_in[2];
    const float* bb  = (const float*)d_in[3];
    const float* Whb = (const float*)d_in[4];
    const float* bhb = (const float*)d_in[5];
    const float* Wr  = (const float*)d_in[6];
    const float* br  = (const float*)d_in[7];
    float* out = (float*)d_out;

    init_kernel<<<(Bb * Hh + 255) / 256, 256>>>();
    transpose_kernel<<<(3 * 262144 + 255) / 256, 256>>>(Whb, Wr, Wb);
    bi_kernel<<<dim3(Hh / NTHR, Ss), NTHR>>>(x, bb);
    seq_kernel<<<NCTA, NTHR>>>(pe, bb, bhb, br, out);
}

// round 9
// speedup vs baseline: 1.4334x; 1.4334x over previous
#include <cuda_runtime.h>
#include <cstdint>
#include <cstddef>

// Dims fixed: B=32, S=512, H=1024, fp32.
#define Bb   32
#define Ss   512
#define Hh   1024
#define NCTA 128
#define NTHR 256
#define RPAD 1028    // padded SMEM row stride (floats): banks (4*r + k) mod 32 disjoint

// ---- device scratch (allocation-free rule: __device__ globals) -------------
// Blocked-transposed weights: WT[m][kq][c][j] = W_m[c][4*kq+j], m in {hb,r,b}.
// float4 index = (m*256 + kq)*1024 + c. 12 MB total (L2-resident).
__device__ __align__(16) float4 g_WT4[3 * 256 * 1024];
__device__ __align__(16) float g_Bi[(size_t)Ss * Bb * Hh]; // tanh(x_t W_b^T + b_b), [t][b][h]
__device__ __align__(16) float g_h [Bb * Hh];
__device__ __align__(16) float g_hi[Bb * Hh];
__device__ __align__(16) float g_ri[Bb * Hh];
__device__ unsigned g_bar;

__global__ void init_kernel() {
    int i = blockIdx.x * blockDim.x + threadIdx.x;
    if (i < Bb * Hh) g_h[i] = 0.0f;
    if (i == 0) g_bar = 0u;
}

// ---------------------------------------------------------------------------
// XLA EmitFastTanh, FMA variant (verified bit-exact in R8): clamp
// +-7.99881172180175781, FMA Horner, |x|<0.0004 passthrough, IEEE divide.
__device__ __forceinline__ float xla_tanh(float x) {
    float z = fminf(x, 7.99881172180175781f);
    z = fmaxf(z, -7.99881172180175781f);
    float x2 = __fmul_rn(z, z);
    float p = __fmaf_rn(x2, -2.76076847742355e-16f, 2.00018790482477e-13f);
    p = __fmaf_rn(x2, p, -8.60467152213735e-11f);
    p = __fmaf_rn(x2, p,  5.12229709037114e-08f);
    p = __fmaf_rn(x2, p,  1.48572235717979e-05f);
    p = __fmaf_rn(x2, p,  6.37261928875436e-04f);
    p = __fmaf_rn(x2, p,  4.89352455891786e-03f);
    p = __fmul_rn(z, p);
    float q = __fmaf_rn(x2, 1.19825839466702e-06f, 1.18534705686654e-04f);
    q = __fmaf_rn(x2, q, 2.26843463243900e-03f);
    q = __fmaf_rn(x2, q, 4.89352518554385e-03f);
    return (fabsf(x) < 0.0004f) ? x : __fdiv_rn(p, q);
}

// ---------------------------------------------------------------------------
// Weight transpose into k-quad-blocked layout. Pure copy (bit-free).
__global__ void transpose_kernel(const float* __restrict__ Whb,
                                 const float* __restrict__ Wr,
                                 const float* __restrict__ Wb) {
    int i = blockIdx.x * blockDim.x + threadIdx.x;   // 0 .. 3*262144-1
    if (i >= 3 * 262144) return;
    int m  = i >> 18;
    int r  = i & 262143;
    int kq = r >> 10;
    int c  = r & 1023;
    const float* src = (m == 0) ? Whb : (m == 1) ? Wr : Wb;
    g_WT4[i] = ((const float4*)src)[c * 256 + kq];
}

// ---------------------------------------------------------------------------
// Bi precompute (unchanged bit order, verified): thread owns column c, 32
// batch accumulators, pure ascending-k fma chains; x panel staged in SMEM
// (warp-uniform LDS broadcasts). FFMA-throughput-bound (~1 ms).
__global__ __launch_bounds__(NTHR, 1) void bi_kernel(
    const float* __restrict__ x, const float* __restrict__ bbias)
{
    __shared__ float xs[Bb][128];
    const int tid = threadIdx.x;
    const int t   = blockIdx.y;
    const int c   = blockIdx.x * NTHR + tid;
    const float4* wt = g_WT4 + 2 * 262144 + c;   // W_b slice, stride 1024 per kq

    float acc[Bb];
    #pragma unroll
    for (int b = 0; b < Bb; b++) acc[b] = 0.0f;

    for (int kp = 0; kp < 8; kp++) {             // 8 panels of 128 k
        __syncthreads();
        #pragma unroll
        for (int j = 0; j < 4; j++) {
            int i  = tid + j * NTHR;             // 0..1023 float4s
            int b  = i >> 5;
            int kl = i & 31;
            ((float4*)&xs[b][0])[kl] =
                *(const float4*)(x + ((size_t)b * Ss + t) * Hh + kp * 128 + kl * 4);
        }
        __syncthreads();
        #pragma unroll 1
        for (int kl = 0; kl < 32; kl++) {
            float4 w = wt[(kp * 32 + kl) * 1024];
            #pragma unroll
            for (int b = 0; b < Bb; b++) {
                float4 a = *(const float4*)&xs[b][kl * 4];
                acc[b] = __fmaf_rn(a.x, w.x, acc[b]);
                acc[b] = __fmaf_rn(a.y, w.y, acc[b]);
                acc[b] = __fmaf_rn(a.z, w.z, acc[b]);
                acc[b] = __fmaf_rn(a.w, w.w, acc[b]);
            }
        }
    }

    float bias = bbias[c];
    #pragma unroll
    for (int b = 0; b < Bb; b++)
        g_Bi[((size_t)t * Bb + b) * Hh + c] = xla_tanh(__fadd_rn(acc[b], bias));
}

// ---------------------------------------------------------------------------
// Grid barrier: release-fence + atomic arrive, acquire poll by tid0.
__device__ __forceinline__ void gsync(unsigned* epoch) {
    *epoch += NCTA;
    __syncthreads();
    if (threadIdx.x == 0) {
        __threadfence();
        atomicAdd(&g_bar, 1u);
        unsigned e = *epoch, v;
        do {
            asm volatile("ld.acquire.gpu.u32 %0, [%1];" : "=r"(v) : "l"(&g_bar));
        } while (v < e);
    }
    __syncthreads();
}

// Canonical dot against SMEM-staged activation row: single accumulator,
// ascending-k fp32 fma chain (bit-identical to the verified R8 order).
// Weight load: 4 lanes share each float4 -> 128B/warp = 1 L1 wavefront.
// Activation: LDS.128, conflict-free with 8-way broadcast.
__device__ __forceinline__ float dot_s(const float4* __restrict__ wt,
                                       const float* __restrict__ sa) {
    float acc = 0.0f;
    #pragma unroll 8
    for (int kq = 0; kq < 256; kq++) {
        float4 w = wt[kq * 1024];
        float4 a = *(const float4*)(sa + kq * 4);
        acc = __fmaf_rn(a.x, w.x, acc);
        acc = __fmaf_rn(a.y, w.y, acc);
        acc = __fmaf_rn(a.z, w.z, acc);
        acc = __fmaf_rn(a.w, w.w, acc);
    }
    return acc;
}

// Stage 8 rows (b0..b0+7) of a [32][1024] global vector into padded SMEM.
__device__ __forceinline__ void stage8(float* __restrict__ s,
                                       const float* __restrict__ src) {
    int tid = threadIdx.x;
    #pragma unroll
    for (int j = 0; j < 8; j++) {
        int i  = tid + j * NTHR;          // 0..2047 float4s
        int r  = i >> 8;
        int kq = i & 255;
        *(float4*)(s + r * RPAD + kq * 4) = ((const float4*)src)[r * 256 + kq];
    }
}

// Stage fl(ri + pe) for 8 rows. Single rounded add per element — exactly the
// op the reference's (ri + p_t) elementwise add performs. Chain order over k
// in the subsequent dot is untouched => bit-exact.
__device__ __forceinline__ void stage8_add(float* __restrict__ s,
                                           const float* __restrict__ r0,
                                           const float* __restrict__ pe,
                                           int b0, int t) {
    int tid = threadIdx.x;
    #pragma unroll
    for (int j = 0; j < 8; j++) {
        int i  = tid + j * NTHR;
        int r  = i >> 8;
        int kq = i & 255;
        float4 a = ((const float4*)r0)[r * 256 + kq];
        float4 q = *(const float4*)(pe + ((size_t)(b0 + r) * Ss + t) * Hh + kq * 4);
        float4 v;
        v.x = __fadd_rn(a.x, q.x); v.y = __fadd_rn(a.y, q.y);
        v.z = __fadd_rn(a.z, q.z); v.w = __fadd_rn(a.w, q.w);
        *(float4*)(s + r * RPAD + kq * 4) = v;
    }
}

// ---------------------------------------------------------------------------
// Sequential recurrence. 128 CTAs x 256 threads; CTA = 32 c x 8 b.
// Warp = 8 c x 4 b: lane = (c_local = lane>>2, b_local = lane&3).
// Weight wavefronts per warp per iter: 1 (vs 4 before); activations via SMEM.
__global__ __launch_bounds__(NTHR, 1) void seq_kernel(
    const float* __restrict__ pe,
    const float* __restrict__ bb, const float* __restrict__ bhb,
    const float* __restrict__ br,
    float* __restrict__ out)
{
    __shared__ float s_act[8 * RPAD];

    const int tid  = threadIdx.x;
    const int lane = tid & 31;
    const int w    = tid >> 5;
    const int cl   = lane >> 2;               // 0..7
    const int bl   = lane & 3;                // 0..3
    const int c    = (blockIdx.x & 31) * 32 + (w & 3) * 8 + cl;
    const int rl   = (w >> 2) * 4 + bl;       // local b row 0..7
    const int b0   = (blockIdx.x >> 5) * 8;
    const int b    = b0 + rl;
    const int o    = b * Hh + c;

    const float4* wt_hb = g_WT4 + 0 * 262144 + c;
    const float4* wt_r  = g_WT4 + 1 * 262144 + c;
    const float4* wt_b  = g_WT4 + 2 * 262144 + c;
    const float bias_hb = bhb[c];
    const float bias_r  = br[c];
    const float bias_b  = bb[c];
    const float* sa     = s_act + rl * RPAD;

    unsigned epoch = 0u;
    float hi = 0.0f;

    #pragma unroll 1
    for (int t = 0; t < Ss; t++) {
        // sub 1: hi = tanh(h @ W_hb^T + b_hb) + bi[t]
        stage8(s_act, g_h + (size_t)b0 * Hh);
        float bi_v = g_Bi[((size_t)t * Bb + b) * Hh + c];   // independent load, early
        __syncthreads();
        float z = dot_s(wt_hb, sa);
        hi = __fadd_rn(xla_tanh(__fadd_rn(z, bias_hb)), bi_v);
        g_hi[o] = hi;
        gsync(&epoch);

        // sub 2: ri = tanh(hi @ W_r^T + b_r)
        stage8(s_act, g_hi + (size_t)b0 * Hh);
        __syncthreads();
        z = dot_s(wt_r, sa);
        g_ri[o] = xla_tanh(__fadd_rn(z, bias_r));
        gsync(&epoch);

        // sub 3: h = hi + tanh((ri + p_t) @ W_b^T + b_b)
        stage8_add(s_act, g_ri + (size_t)b0 * Hh, pe, b0, t);
        __syncthreads();
        z = dot_s(wt_b, sa);
        float hn = __fadd_rn(hi, xla_tanh(__fadd_rn(z, bias_b)));
        g_h[o] = hn;
        if (t == Ss - 1) out[o] = hn;
        gsync(&epoch);
    }
}

// ---------------------------------------------------------------------------
extern "C" void kernel_launch(void* const* d_in, const int* in_sizes, int n_in,
                              void* d_out, int out_size) {
    const float* x   = (const float*)d_in[0];
    const float* pe  = (const float*)d_in[1];
    const float* Wb  = (const float*)d_in[2];
    const float* bb  = (const float*)d_in[3];
    const float* Whb = (const float*)d_in[4];
    const float* bhb = (const float*)d_in[5];
    const float* Wr  = (const float*)d_in[6];
    const float* br  = (const float*)d_in[7];
    float* out = (float*)d_out;

    init_kernel<<<(Bb * Hh + 255) / 256, 256>>>();
    transpose_kernel<<<(3 * 262144 + 255) / 256, 256>>>(Whb, Wr, Wb);
    bi_kernel<<<dim3(Hh / NTHR, Ss), NTHR>>>(x, bb);
    seq_kernel<<<NCTA, NTHR>>>(pe, bb, bhb, br, out);
}